// round 1
// baseline (speedup 1.0000x reference)
#include <cuda_runtime.h>

#define NB 64      // batch
#define NC 64      // in channels
#define NH 32
#define NW 32
#define NOC 128
#define NL 1024
#define PH 34      // padded spatial

#define SA 72      // A smem row stride (floats), 72 % 32 == 8 -> conflict-free frag loads
#define SB 136     // B smem row stride (floats), 136 % 32 == 8
#define A_BUF (64 * SA)
#define B_BUF (64 * SB)
#define STAGE_ELEMS (A_BUF + B_BUF)
#define SMEM_ELEMS (2 * STAGE_ELEMS + NOC)
#define SMEM_BYTES (SMEM_ELEMS * 4)

// Scratch: x transposed to [c][y][x][b] (batch innermost), padded by 1, tf32-rounded bits.
__device__ unsigned int g_xTp[NC * PH * PH * NB];

// ---------------------------------------------------------------------------
// Kernel 1: transpose + pad + tf32 round.  grid (34, 64) = (y, c), 256 thr.
// ---------------------------------------------------------------------------
__global__ void __launch_bounds__(256) transpose_pad_kernel(const float* __restrict__ x) {
    __shared__ unsigned int s[NB * 33];
    int y = blockIdx.x;      // padded row 0..33
    int c = blockIdx.y;      // channel
    int tid = threadIdx.x;
    unsigned int* dst = g_xTp + (size_t)(c * PH + y) * (PH * NB);
    if (y == 0 || y == PH - 1) {
        for (int idx = tid; idx < PH * NB; idx += 256) dst[idx] = 0u;
        return;
    }
    // read x[b][c][y-1][x0] coalesced over x0
    for (int idx = tid; idx < NB * NW; idx += 256) {
        int b = idx >> 5, x0 = idx & 31;
        float v = x[(((size_t)b * NC + c) * NH + (y - 1)) * NW + x0];
        unsigned int t;
        asm("cvt.rna.tf32.f32 %0, %1;" : "=r"(t) : "f"(v));
        s[b * 33 + x0] = t;
    }
    __syncthreads();
    // write [x0][b] contiguous (b innermost) coalesced
    for (int idx = tid; idx < PH * NB; idx += 256) {
        int x0 = idx >> 6, b = idx & 63;
        dst[idx] = (x0 == 0 || x0 == PH - 1) ? 0u : s[b * 33 + (x0 - 1)];
    }
}

// ---------------------------------------------------------------------------
// Kernel 2: per-location GEMM  C[64b x 128o] = A[64b x 576d] * B[576d x 128o]
// grid = 1024 (one CTA per l), 256 threads = 8 warps (2x4 of 32x32 tiles).
// K loop = 9 taps x 64 channels, cp.async double-buffered.
// ---------------------------------------------------------------------------
__device__ __forceinline__ void cp16(unsigned int saddr, const void* g) {
    asm volatile("cp.async.cg.shared.global [%0], [%1], 16;" :: "r"(saddr), "l"(g));
}
__device__ __forceinline__ unsigned int f2tf(float v) {
    unsigned int t;
    asm("cvt.rna.tf32.f32 %0, %1;" : "=r"(t) : "f"(v));
    return t;
}

__global__ void __launch_bounds__(256, 2) lc_gemm_kernel(
    const float* __restrict__ w, const float* __restrict__ bias,
    float* __restrict__ out)
{
    extern __shared__ unsigned int sm[];
    int l = blockIdx.x;
    int oh = l >> 5, ow = l & 31;
    int tid = threadIdx.x;
    int lane = tid & 31;
    int wid = tid >> 5;
    int m_base = (wid >> 2) * 32;   // batch tile base
    int n_base = (wid & 3) * 32;    // OC tile base

    unsigned int smem_base = (unsigned int)__cvta_generic_to_shared(sm);
    float* sbias = (float*)(sm + 2 * STAGE_ELEMS);

    // bias[o][l] for this location
    for (int o = tid; o < NOC; o += 256)
        sbias[o] = bias[(size_t)o * NL + l];

    const float* wl = w + (size_t)l * NOC;   // + d*NL*NOC + o

    auto load_tap = [&](int ii, int st) {
        int iy = oh + ii / 3;
        int ix = ow + ii % 3;
        unsigned int sA = smem_base + (unsigned)(st * STAGE_ELEMS) * 4u;
        unsigned int sB = sA + A_BUF * 4;
        const unsigned int* xsrc = g_xTp + ((size_t)iy * PH + ix) * NB;
        // A: 64 c-rows x 64 b floats = 1024 float4
        #pragma unroll
        for (int f = 0; f < 4; ++f) {
            int t = tid + f * 256;
            int c = t >> 4;
            int b4 = (t & 15) << 2;
            cp16(sA + (unsigned)(c * SA + b4) * 4u,
                 xsrc + (size_t)c * (PH * PH * NB) + b4);
        }
        // B: 64 d-rows x 128 o floats = 2048 float4, d = c*9 + ii
        #pragma unroll
        for (int f = 0; f < 8; ++f) {
            int t = tid + f * 256;
            int c = t >> 5;
            int o4 = (t & 31) << 2;
            cp16(sB + (unsigned)(c * SB + o4) * 4u,
                 wl + (size_t)(c * 9 + ii) * (NL * NOC) + o4);
        }
    };

    float acc[2][4][4];
    #pragma unroll
    for (int mt = 0; mt < 2; ++mt)
        #pragma unroll
        for (int nt = 0; nt < 4; ++nt)
            #pragma unroll
            for (int q = 0; q < 4; ++q) acc[mt][nt][q] = 0.f;

    load_tap(0, 0);
    asm volatile("cp.async.commit_group;");

    for (int s = 0; s < 9; ++s) {
        if (s + 1 < 9) {
            load_tap(s + 1, (s + 1) & 1);
            asm volatile("cp.async.commit_group;");
            asm volatile("cp.async.wait_group 1;");
        } else {
            asm volatile("cp.async.wait_group 0;");
        }
        __syncthreads();

        const unsigned int* As = sm + (s & 1) * STAGE_ELEMS;
        const float* Bs = (const float*)(As + A_BUF);
        int kc = lane & 3, r = lane >> 2;

        #pragma unroll
        for (int k8 = 0; k8 < 8; ++k8) {
            int kb = k8 * 8;
            unsigned int a[2][4], bf[4][2];
            #pragma unroll
            for (int mt = 0; mt < 2; ++mt) {
                int mrow = m_base + mt * 16 + r;
                a[mt][0] = As[(kb + kc) * SA + mrow];
                a[mt][1] = As[(kb + kc) * SA + mrow + 8];
                a[mt][2] = As[(kb + kc + 4) * SA + mrow];
                a[mt][3] = As[(kb + kc + 4) * SA + mrow + 8];
            }
            #pragma unroll
            for (int nt = 0; nt < 4; ++nt) {
                int col = n_base + nt * 8 + r;
                bf[nt][0] = f2tf(Bs[(kb + kc) * SB + col]);
                bf[nt][1] = f2tf(Bs[(kb + kc + 4) * SB + col]);
            }
            #pragma unroll
            for (int mt = 0; mt < 2; ++mt)
                #pragma unroll
                for (int nt = 0; nt < 4; ++nt) {
                    asm volatile(
                        "mma.sync.aligned.m16n8k8.row.col.f32.tf32.tf32.f32 "
                        "{%0,%1,%2,%3}, {%4,%5,%6,%7}, {%8,%9}, {%0,%1,%2,%3};"
                        : "+f"(acc[mt][nt][0]), "+f"(acc[mt][nt][1]),
                          "+f"(acc[mt][nt][2]), "+f"(acc[mt][nt][3])
                        : "r"(a[mt][0]), "r"(a[mt][1]), "r"(a[mt][2]), "r"(a[mt][3]),
                          "r"(bf[nt][0]), "r"(bf[nt][1]));
                }
        }
        __syncthreads();
    }

    // Epilogue: out[b][o][l] += bias[o][l].  Scattered 4B stores; the 8 CTAs
    // covering l..l+7 share each 32B sector and merge in L2 (out fits in L2).
    #pragma unroll
    for (int mt = 0; mt < 2; ++mt) {
        int r0 = m_base + mt * 16 + (lane >> 2);
        #pragma unroll
        for (int nt = 0; nt < 4; ++nt) {
            int col0 = n_base + nt * 8 + 2 * (lane & 3);
            float bz0 = sbias[col0], bz1 = sbias[col0 + 1];
            float* p0 = out + (size_t)r0 * (NOC * NL) + (size_t)col0 * NL + l;
            p0[0]                         = acc[mt][nt][0] + bz0;
            p0[NL]                        = acc[mt][nt][1] + bz1;
            p0[(size_t)8 * NOC * NL]      = acc[mt][nt][2] + bz0;
            p0[(size_t)8 * NOC * NL + NL] = acc[mt][nt][3] + bz1;
        }
    }
}

// ---------------------------------------------------------------------------
extern "C" void kernel_launch(void* const* d_in, const int* in_sizes, int n_in,
                              void* d_out, int out_size) {
    const float* x    = (const float*)d_in[0];   // (64,64,32,32)
    const float* wgt  = (const float*)d_in[1];   // (1,576,1024,128)
    const float* bias = (const float*)d_in[2];   // (1,128,32,32)
    float* out = (float*)d_out;                  // (64,128,32,32)

    cudaFuncSetAttribute(lc_gemm_kernel,
                         cudaFuncAttributeMaxDynamicSharedMemorySize, SMEM_BYTES);

    transpose_pad_kernel<<<dim3(PH, NC), 256>>>(x);
    lc_gemm_kernel<<<NL, 256, SMEM_BYTES>>>(wgt, bias, out);
}